// round 9
// baseline (speedup 1.0000x reference)
#include <cuda_runtime.h>
#include <cstdint>

#define HWC 4096
#define NSLICES 8192
#define NBLK 1024                          // 8 slices per block, one per warp
#define NPART 32
#define NL1 32
#define L1_TARGET (NBLK / NL1)             // 32

#define CWG_F  (-2.0f    / 33554432.0f)
#define DCML_F (-0.01f   / 33554432.0f)
#define TV_F   (1.0e-4f  / 16128.0f)
#define RCUT2  324.0f                      // 18^2; truncation ~5.5e-5 rel (measured)

__device__ float    g_partial[NPART];
__device__ unsigned g_t1[NL1];
__device__ unsigned g_t2;

__device__ __forceinline__ float fsqrt_approx(float x) {
    float y; asm("sqrt.approx.f32 %0, %1;" : "=f"(y) : "f"(x)); return y;
}
__device__ __forceinline__ float fex2(float x) {
    float y; asm("ex2.approx.f32 %0, %1;" : "=f"(y) : "f"(x)); return y;
}

__device__ __forceinline__ void ticket_and_finalize(int blk, float* __restrict__ out) {
    const unsigned t1 = atomicAdd(&g_t1[blk & (NL1 - 1)], 1u);
    if (t1 == (unsigned)(L1_TARGET - 1)) {
        g_t1[blk & (NL1 - 1)] = 0u;
        const unsigned t2 = atomicAdd(&g_t2, 1u);
        if (t2 == (unsigned)(NL1 - 1)) {
            float s = 0.0f;
#pragma unroll
            for (int i = 0; i < NPART; i++)
                s += atomicExch(&g_partial[i], 0.0f);
            out[0] = s;
            atomicExch(&g_t2, 0u);
        }
    }
}

// 1024 blocks x 256 threads. Warp w of block b owns slice b*8+w.
// Blocks 0..255 additionally own one TV/DCML line (threads < 64).
__global__ void __launch_bounds__(256) fused_kernel(
    const float* __restrict__ sim,
    const float* __restrict__ wc,
    const int*  __restrict__ mask,
    float*      __restrict__ out)
{
    const int j   = threadIdx.x;
    const int blk = blockIdx.x;
    const int w   = j >> 5;
    const int l   = j & 31;
    float total = 0.0f;

    // ---- TV + DCML: blocks 0..255 each own one row/col line ----
    if (blk < 256) {
        __shared__ float c0[64], c1[64], m[64];
        const int orient = blk >> 7;       // 0: row lines (use x), 1: col lines (use y)
        const int b      = (blk >> 6) & 1;
        const int line   = blk & 63;
        if (j < 64) {
            int p = (orient == 0) ? (b * HWC + line * 64 + j)
                                  : (b * HWC + j * 64 + line);
            c0[j] = wc[2 * p + 0];
            c1[j] = wc[2 * p + 1];
            m[j]  = mask[p] ? 1.0f : 0.0f;
        }
        __syncthreads();
        if (j < 64) {
            float dc = 0.0f;
            const float vj = orient ? c0[j] : c1[j];
            if (m[j] != 0.0f) {
                for (int q = j + 1; q < 64; q++)
                    dc += fmaxf((orient ? c0[q] : c1[q]) - vj, 0.0f) * m[q];
            }
            float tv = 0.0f;
            if (j < 63) {
                const float d0 = c0[j + 1] - c0[j];
                const float d1 = c1[j + 1] - c1[j];
                tv = (d0 * d0 + d1 * d1) * m[j] * m[j + 1];
            }
            total = dc * DCML_F + tv * TV_F;
        }
        __syncthreads();
    }

    // ---- CWG: this warp's slice ----
    const int slice = blk * 8 + w;
    if (mask[slice]) {
        const float wcy = wc[2 * slice + 0];
        const float wcx = wc[2 * slice + 1];
        const float4* s4 = (const float4*)(sim + (size_t)slice * 4096);
        const float K = -0.72134752044448169f;   // -0.5*log2(e)

        // lane geometry: col fixed per lane; rows advance by 2 per chunk
        const float a0 = (float)((l & 15) * 4) - wcx;
        float ax2[4];
#pragma unroll
        for (int k = 0; k < 4; k++) ax2[k] = (a0 + (float)k) * (a0 + (float)k);
        const float dxn  = fmaxf(fmaxf(a0, -a0 - 3.0f), 0.0f);
        const float dxn2 = dxn * dxn;
        const float dyb  = (float)(l >> 4) - wcy;   // lane's row parity offset

        float cacc = 0.0f;
#pragma unroll
        for (int g = 0; g < 8; g++) {               // 8-row groups: band skip
            const float dyg = dyb + (float)(8 * g);
            if (dyg < 18.0f && dyg > -24.0f) {
                float4 v[4]; float dy2[4];
#pragma unroll
                for (int c = 0; c < 4; c++) {       // disk-predicated loads, batched
                    const float dy = dyg + (float)(2 * c);
                    dy2[c] = dy * dy;
                    const bool pr = (dy2[c] + dxn2) < RCUT2;
                    v[c] = pr ? s4[(g * 4 + c) * 32 + l]
                              : make_float4(0.f, 0.f, 0.f, 0.f);
                }
#pragma unroll
                for (int c = 0; c < 4; c++) {       // unguarded: zero lanes add 0
                    const float d2 = dy2[c];
                    cacc += v[c].x * fex2(K * fsqrt_approx(d2 + ax2[0]));
                    cacc += v[c].y * fex2(K * fsqrt_approx(d2 + ax2[1]));
                    cacc += v[c].z * fex2(K * fsqrt_approx(d2 + ax2[2]));
                    cacc += v[c].w * fex2(K * fsqrt_approx(d2 + ax2[3]));
                }
            }
        }
        total += cacc * CWG_F;
    }

    // ---- reduce: warp shfl -> smem -> warp0 -> one atomic + ticket ----
#pragma unroll
    for (int o = 16; o; o >>= 1) total += __shfl_down_sync(0xffffffffu, total, o);
    __shared__ float sh[8];
    if (l == 0) sh[w] = total;
    __syncthreads();
    if (j == 0) {
        float s = 0.0f;
#pragma unroll
        for (int ww = 0; ww < 8; ww++) s += sh[ww];
        atomicAdd(&g_partial[blk & (NPART - 1)], s);
        __threadfence();
        ticket_and_finalize(blk, out);
    }
}

extern "C" void kernel_launch(void* const* d_in, const int* in_sizes, int n_in,
                              void* d_out, int out_size)
{
    const float* sim  = (const float*)d_in[0];
    const float* wc   = (const float*)d_in[1];
    const int*   mask = (const int*)d_in[2];
    float* out = (float*)d_out;

    fused_kernel<<<NBLK, 256>>>(sim, wc, mask, out);
}